// round 3
// baseline (speedup 1.0000x reference)
#include <cuda_runtime.h>
#include <cuda_bf16.h>

typedef unsigned long long ull;

#define NC 173
#define NL 400
#define NB 64
#define FEAT_PER_C 320          // 32 ch * 10 pool
#define NFEAT (NC * FEAT_PER_C) // 55360
#define KSPLIT 16
#define KCH (NFEAT / KSPLIT)    // 3460

__device__ float g_feat[NB * NFEAT];          // pooled features [b][55360]
__device__ float g_part[KSPLIT * NB * 128];   // FC1 partials [ks][b][j]

// ---------- packed f32x2 helpers (sm_103a FFMA2) ----------
__device__ __forceinline__ ull fma2(ull a, ull b, ull c) {
    ull d;
    asm("fma.rn.f32x2 %0, %1, %2, %3;" : "=l"(d) : "l"(a), "l"(b), "l"(c));
    return d;
}
__device__ __forceinline__ ull pack2(float lo, float hi) {
    ull d;
    asm("mov.b64 %0, {%1, %2};" : "=l"(d) : "f"(lo), "f"(hi));
    return d;
}
__device__ __forceinline__ float2 unpack2(ull v) {
    float2 r;
    asm("mov.b64 {%0, %1}, %2;" : "=f"(r.x), "=f"(r.y) : "l"(v));
    return r;
}

// =====================================================================
// Kernel A: one block per (b, c). conv1+BN+ReLU -> conv2+BN+ReLU -> pool
// =====================================================================
__global__ __launch_bounds__(256) void tower_kernel(
    const float* __restrict__ x,
    const float* __restrict__ w1g, const float* __restrict__ b1,
    const float* __restrict__ g1,  const float* __restrict__ beta1,
    const float* __restrict__ m1,  const float* __restrict__ v1,
    const float* __restrict__ w2g, const float* __restrict__ b2,
    const float* __restrict__ g2,  const float* __restrict__ beta2,
    const float* __restrict__ m2,  const float* __restrict__ v2)
{
    __shared__ float xs[408];            // x with pad-4 halo
    __shared__ float w1s[144];           // 16 x 9
    __shared__ float s1s[16], t1s[16];   // folded BN1
    __shared__ float y1s[16 * 408];      // conv1 output, 3-zero halo each side
    __shared__ float2 w2p[16 * 7 * 16];  // [i][k][opair] interleaved pairs
    __shared__ float2 s2p[16], t2p[16];  // folded BN2 per o-pair
    __shared__ int pool_s[FEAT_PER_C];   // pooled maxima as int bits (vals >= 0)

    const int bc = blockIdx.x;
    const int b = bc / NC, c = bc - b * NC;
    const int tid = threadIdx.x;

    // ---------------- phase 0: stage everything ----------------
    const float* xrow = x + bc * NL;
    for (int idx = tid; idx < 408; idx += 256)
        xs[idx] = (idx >= 4 && idx < 404) ? xrow[idx - 4] : 0.f;
    if (tid < 144) w1s[tid] = w1g[c * 144 + tid];
    if (tid >= 144 && tid < 160) {
        int f = tid - 144, cf = c * 16 + f;
        float s = g1[cf] * rsqrtf(v1[cf] + 1e-5f);
        s1s[f] = s;
        t1s[f] = s * (b1[cf] - m1[cf]) + beta1[cf];
    }
    if (tid >= 160 && tid < 176) {
        int pr = tid - 160;
        int o0 = c * 32 + 2 * pr, o1 = o0 + 1;
        float sa = g2[o0] * rsqrtf(v2[o0] + 1e-5f);
        float sb = g2[o1] * rsqrtf(v2[o1] + 1e-5f);
        s2p[pr] = make_float2(sa, sb);
        t2p[pr] = make_float2(sa * (b2[o0] - m2[o0]) + beta2[o0],
                              sb * (b2[o1] - m2[o1]) + beta2[o1]);
    }
    if (tid < 96) {                       // zero y1 halos
        int i = tid / 6, jj = tid - 6 * (tid / 6);
        y1s[i * 408 + (jj < 3 ? jj : 400 + jj)] = 0.f;
    }
    for (int idx = tid; idx < FEAT_PER_C; idx += 256)   // FIX: 320 > 256
        pool_s[idx] = 0;
    // w2 interleave: w2p[(i*7+k)*16 + pr] = {w2[o=2pr], w2[o=2pr+1]}
    {
        const float* wcbase = w2g + c * 3584;   // [o][i][k], o stride 112
        for (int idx = tid; idx < 1792; idx += 256) {
            int pr = idx & 15, ik = idx >> 4;
            int i = ik / 7, k = ik - i * 7;
            const float* wb = wcbase + i * 7 + k;
            w2p[idx] = make_float2(wb[(2 * pr) * 112], wb[(2 * pr + 1) * 112]);
        }
    }
    __syncthreads();

    // ---------------- phase 1: conv1 (16 x 400), BN, ReLU ----------------
    for (int idx = tid; idx < 6400; idx += 256) {
        int f = idx / 400, t = idx - f * 400;
        const float* wf = &w1s[f * 9];
        float a = 0.f;
#pragma unroll
        for (int k = 0; k < 9; ++k) a = fmaf(wf[k], xs[t + k], a);
        y1s[f * 408 + 3 + t] = fmaxf(fmaf(s1s[f], a, t1s[f]), 0.f);
    }
    __syncthreads();

    // ------------- phase 2: conv2 (32 x 400) via FFMA2, BN, ReLU, pool -------------
    if (tid < 200) {
        const int pg = tid >> 2;       // position tile 0..49  (8 positions each)
        const int cg = tid & 3;        // channel group: pairs [cg*4, cg*4+4)
        const int t0 = pg * 8;

        ull acc[4][8];
#pragma unroll
        for (int pp = 0; pp < 4; ++pp)
#pragma unroll
            for (int t = 0; t < 8; ++t) acc[pp][t] = 0ull;

        const ull* w2u = reinterpret_cast<const ull*>(w2p);

#pragma unroll 1
        for (int i = 0; i < 16; ++i) {
            const float* yb = &y1s[i * 408 + t0];   // halo already offsets by 3
            ull yp[14];
#pragma unroll
            for (int j = 0; j < 14; ++j) {
                float v = yb[j];
                yp[j] = pack2(v, v);
            }
            const ull* wrow = w2u + (i * 7) * 16 + cg * 4;
#pragma unroll
            for (int k = 0; k < 7; ++k) {
#pragma unroll
                for (int pp = 0; pp < 4; ++pp) {
                    ull wp = wrow[k * 16 + pp];
#pragma unroll
                    for (int t = 0; t < 8; ++t)
                        acc[pp][t] = fma2(wp, yp[t + k], acc[pp][t]);
                }
            }
        }

        // epilogue: BN2, ReLU (via max-with-0), pool max over the 8 positions
        const ull* s2u = reinterpret_cast<const ull*>(s2p);
        const ull* t2u = reinterpret_cast<const ull*>(t2p);
        const int pw = t0 / 40;
#pragma unroll
        for (int pp = 0; pp < 4; ++pp) {
            int pr = cg * 4 + pp;
            ull sc = s2u[pr], bi = t2u[pr];
            float mlo = 0.f, mhi = 0.f;
#pragma unroll
            for (int t = 0; t < 8; ++t) {
                float2 v = unpack2(fma2(acc[pp][t], sc, bi));
                mlo = fmaxf(mlo, v.x);
                mhi = fmaxf(mhi, v.y);
            }
            atomicMax(&pool_s[(2 * pr) * 10 + pw], __float_as_int(mlo));
            atomicMax(&pool_s[(2 * pr + 1) * 10 + pw], __float_as_int(mhi));
        }
    }
    __syncthreads();

    // ---------------- phase 3: write pooled features ----------------
    for (int idx = tid; idx < FEAT_PER_C; idx += 256)   // FIX: 320 > 256
        g_feat[b * NFEAT + c * FEAT_PER_C + idx] = __int_as_float(pool_s[idx]);
}

// =====================================================================
// Kernel B: FC1, tiled, K-split into deterministic partial buffer
// grid (16 j-tiles, KSPLIT k-splits), 128 threads
// =====================================================================
__global__ __launch_bounds__(128) void fc1_kernel(const float* __restrict__ wc1)
{
    __shared__ float fs[64 * 65];
    __shared__ float ws[8 * 65];

    const int jt = blockIdx.x, ks = blockIdx.y;
    const int tid = threadIdx.x;
    const int b = tid & 63, jh = tid >> 6;
    const int kbeg = ks * KCH, kend = kbeg + KCH;

    float acc[4] = {0.f, 0.f, 0.f, 0.f};

    for (int k0 = kbeg; k0 < kend; k0 += 64) {
#pragma unroll 8
        for (int l = 0; l < 32; ++l) {
            int idx = tid + l * 128;
            int r = idx >> 6, cc = idx & 63;
            int k = k0 + cc;
            fs[r * 65 + cc] = (k < kend) ? g_feat[r * NFEAT + k] : 0.f;
        }
#pragma unroll
        for (int l = 0; l < 4; ++l) {
            int idx = tid + l * 128;
            int r = idx >> 6, cc = idx & 63;
            int k = k0 + cc;
            ws[r * 65 + cc] = (k < kend) ? wc1[(jt * 8 + r) * NFEAT + k] : 0.f;
        }
        __syncthreads();
#pragma unroll
        for (int cc = 0; cc < 64; ++cc) {
            float f = fs[b * 65 + cc];
#pragma unroll
            for (int r = 0; r < 4; ++r)
                acc[r] += f * ws[(jh * 4 + r) * 65 + cc];
        }
        __syncthreads();
    }
#pragma unroll
    for (int r = 0; r < 4; ++r)
        g_part[(ks * 64 + b) * 128 + jt * 8 + jh * 4 + r] = acc[r];
}

// =====================================================================
// Kernel C: reduce partials, bias1, ReLU, FC2
// grid 64 (batch), 128 threads (one per hidden unit)
// =====================================================================
__global__ __launch_bounds__(128) void fc2_kernel(
    const float* __restrict__ bc1, const float* __restrict__ wc2,
    const float* __restrict__ bc2, float* __restrict__ out)
{
    const int b = blockIdx.x, j = threadIdx.x;
    float s = bc1[j];
#pragma unroll
    for (int ks = 0; ks < KSPLIT; ++ks)
        s += g_part[(ks * 64 + b) * 128 + j];
    float v = fmaxf(s, 0.f) * wc2[j];
#pragma unroll
    for (int o = 16; o > 0; o >>= 1)
        v += __shfl_down_sync(0xffffffffu, v, o);
    __shared__ float red[4];
    if ((j & 31) == 0) red[j >> 5] = v;
    __syncthreads();
    if (j == 0) out[b] = red[0] + red[1] + red[2] + red[3] + bc2[0];
}

// =====================================================================
extern "C" void kernel_launch(void* const* d_in, const int* in_sizes, int n_in,
                              void* d_out, int out_size)
{
    const float* x     = (const float*)d_in[0];
    const float* w1    = (const float*)d_in[1];
    const float* b1    = (const float*)d_in[2];
    const float* g1    = (const float*)d_in[3];
    const float* beta1 = (const float*)d_in[4];
    const float* m1    = (const float*)d_in[5];
    const float* v1    = (const float*)d_in[6];
    const float* w2    = (const float*)d_in[7];
    const float* b2    = (const float*)d_in[8];
    const float* g2    = (const float*)d_in[9];
    const float* beta2 = (const float*)d_in[10];
    const float* m2    = (const float*)d_in[11];
    const float* v2    = (const float*)d_in[12];
    const float* wc1   = (const float*)d_in[13];
    const float* bc1   = (const float*)d_in[14];
    const float* wc2   = (const float*)d_in[15];
    const float* bc2   = (const float*)d_in[16];
    float* out = (float*)d_out;

    tower_kernel<<<NB * NC, 256>>>(x, w1, b1, g1, beta1, m1, v1,
                                   w2, b2, g2, beta2, m2, v2);
    fc1_kernel<<<dim3(16, KSPLIT), 128>>>(wc1);
    fc2_kernel<<<NB, 128>>>(bc1, wc2, bc2, out);
}

// round 5
// speedup vs baseline: 2.0588x; 2.0588x over previous
#include <cuda_runtime.h>
#include <cuda_bf16.h>

typedef unsigned long long ull;

#define NC 173
#define NL 400
#define NB 64
#define FEAT_PER_C 320          // 32 ch * 10 pool
#define NFEAT (NC * FEAT_PER_C) // 55360
#define KSPLIT 160
#define KCH (NFEAT / KSPLIT)    // 346

#define Y1S 416                 // y1 row stride (left halo 7, right pad)

__device__ float  g_feat[NB * NFEAT];          // pooled features [b][55360]
__device__ float  g_part[KSPLIT * NB * 128];   // FC1 partials [ks][b][j]
__device__ float  g_w1f[NC * 144];             // BN1-folded conv1 weights
__device__ float  g_t1 [NC * 16];              // BN1-folded bias
__device__ __align__(16) float2 g_w2i[NC * 1792]; // BN2-folded interleaved conv2 weights
__device__ float2 g_t2 [NC * 16];              // BN2-folded bias pairs

// ---------- packed f32x2 helpers (sm_103a FFMA2) ----------
__device__ __forceinline__ ull fma2(ull a, ull b, ull c) {
    ull d;
    asm("fma.rn.f32x2 %0, %1, %2, %3;" : "=l"(d) : "l"(a), "l"(b), "l"(c));
    return d;
}
__device__ __forceinline__ ull add2(ull a, ull b) {
    ull d;
    asm("add.rn.f32x2 %0, %1, %2;" : "=l"(d) : "l"(a), "l"(b));
    return d;
}
__device__ __forceinline__ ull pack2(float lo, float hi) {
    ull d;
    asm("mov.b64 %0, {%1, %2};" : "=l"(d) : "f"(lo), "f"(hi));
    return d;
}
__device__ __forceinline__ float2 unpack2(ull v) {
    float2 r;
    asm("mov.b64 {%0, %1}, %2;" : "=f"(r.x), "=f"(r.y) : "l"(v));
    return r;
}

// =====================================================================
// Kernel P: per-channel weight prep (BN fold + conv2 pair interleave)
// grid NC, 256 threads
// =====================================================================
__global__ __launch_bounds__(256) void prep_kernel(
    const float* __restrict__ w1g, const float* __restrict__ b1,
    const float* __restrict__ g1,  const float* __restrict__ beta1,
    const float* __restrict__ m1,  const float* __restrict__ v1,
    const float* __restrict__ w2g, const float* __restrict__ b2,
    const float* __restrict__ g2,  const float* __restrict__ beta2,
    const float* __restrict__ m2,  const float* __restrict__ v2)
{
    __shared__ float s1s[16], s2s[32], t2s[32];
    const int c = blockIdx.x, tid = threadIdx.x;

    if (tid < 16) {
        int cf = c * 16 + tid;
        float s = g1[cf] * rsqrtf(v1[cf] + 1e-5f);
        s1s[tid] = s;
        g_t1[cf] = s * (b1[cf] - m1[cf]) + beta1[cf];
    }
    if (tid >= 32 && tid < 64) {
        int o = tid - 32, co = c * 32 + o;
        float s = g2[co] * rsqrtf(v2[co] + 1e-5f);
        s2s[o] = s;
        t2s[o] = s * (b2[co] - m2[co]) + beta2[co];
    }
    __syncthreads();

    if (tid < 144)
        g_w1f[c * 144 + tid] = w1g[c * 144 + tid] * s1s[tid / 9];
    if (tid >= 144 && tid < 160) {
        int pr = tid - 144;
        g_t2[c * 16 + pr] = make_float2(t2s[2 * pr], t2s[2 * pr + 1]);
    }
    // interleave: g_w2i[c][(i*7+k)*16 + pr] = {s*w2[o=2pr], s*w2[o=2pr+1]}
    const float* wc = w2g + c * 3584;     // [o][i][k], o-stride 112
    for (int idx = tid; idx < 1792; idx += 256) {
        int pr = idx & 15, ik = idx >> 4;
        int i = ik / 7, k = ik - i * 7;
        int o0 = 2 * pr;
        g_w2i[c * 1792 + idx] = make_float2(wc[o0 * 112 + i * 7 + k] * s2s[o0],
                                            wc[(o0 + 1) * 112 + i * 7 + k] * s2s[o0 + 1]);
    }
}

// =====================================================================
// Kernel A: one block per (b, c). conv1 -> conv2 (FFMA2) -> pool
// =====================================================================
__global__ __launch_bounds__(256) void tower_kernel(const float* __restrict__ x)
{
    __shared__ __align__(16) float xs[408];           // x with pad-4 halo
    __shared__ float w1s[144];                        // folded 16x9
    __shared__ float t1s[16];
    __shared__ __align__(16) float y1s[16 * Y1S];     // conv1 out, halo-7 left
    __shared__ __align__(16) float2 w2p[16 * 7 * 16]; // [i][k][opair]
    __shared__ float2 t2p[16];
    __shared__ int pool_s[FEAT_PER_C];

    const int bc = blockIdx.x;
    const int b = bc / NC, c = bc - b * NC;
    const int tid = threadIdx.x;

    // ---------------- phase 0: coalesced staging ----------------
    const float* xrow = x + bc * NL;
    for (int idx = tid; idx < 408; idx += 256)
        xs[idx] = (idx >= 4 && idx < 404) ? xrow[idx - 4] : 0.f;
    if (tid < 144) w1s[tid] = g_w1f[c * 144 + tid];
    if (tid >= 144 && tid < 160) t1s[tid - 144] = g_t1[c * 16 + tid - 144];
    if (tid >= 160 && tid < 176) t2p[tid - 160] = g_t2[c * 16 + tid - 160];
    {   // w2p copy: 1792 float2 = 896 float4
        const float4* src = reinterpret_cast<const float4*>(g_w2i + c * 1792);
        float4* dst = reinterpret_cast<float4*>(w2p);
        for (int idx = tid; idx < 896; idx += 256) dst[idx] = src[idx];
    }
    if (tid < 256) {     // zero y1 halos: cols 0..6 and 407..415 (16 per row)
        int i = tid >> 4, jj = tid & 15;
        y1s[i * Y1S + (jj < 7 ? jj : 400 + jj)] = 0.f;
    }
    for (int idx = tid; idx < FEAT_PER_C; idx += 256) pool_s[idx] = 0;
    __syncthreads();

    // ---------------- phase 1: conv1 (16 x 400) + bias + ReLU ----------------
    for (int idx = tid; idx < 6400; idx += 256) {
        int f = idx / 400, t = idx - f * 400;
        const float* wf = &w1s[f * 9];
        float a = 0.f;
#pragma unroll
        for (int k = 0; k < 9; ++k) a = fmaf(wf[k], xs[t + k], a);
        y1s[f * Y1S + 7 + t] = fmaxf(a + t1s[f], 0.f);
    }
    __syncthreads();

    // ------------- phase 2: conv2 (32 x 400) FFMA2 + bias + ReLU + pool -------------
    if (tid < 200) {
        const int pg = tid >> 2;       // position tile 0..49 (8 positions)
        const int cg = tid & 3;        // pair group: pairs [cg*4, cg*4+4)
        const int t0 = pg * 8;

        ull acc[4][8];
#pragma unroll
        for (int pp = 0; pp < 4; ++pp)
#pragma unroll
            for (int t = 0; t < 8; ++t) acc[pp][t] = 0ull;

#pragma unroll 1
        for (int i = 0; i < 16; ++i) {
            // 14-float window, 16B aligned: cols t0+4 .. t0+17
            const float* ybase = &y1s[i * Y1S + t0 + 4];
            float4 a0 = *reinterpret_cast<const float4*>(ybase);
            float4 a1 = *reinterpret_cast<const float4*>(ybase + 4);
            float4 a2 = *reinterpret_cast<const float4*>(ybase + 8);
            float2 a3 = *reinterpret_cast<const float2*>(ybase + 12);
            ull yp[14];
            yp[0] = pack2(a0.x, a0.x);  yp[1] = pack2(a0.y, a0.y);
            yp[2] = pack2(a0.z, a0.z);  yp[3] = pack2(a0.w, a0.w);
            yp[4] = pack2(a1.x, a1.x);  yp[5] = pack2(a1.y, a1.y);
            yp[6] = pack2(a1.z, a1.z);  yp[7] = pack2(a1.w, a1.w);
            yp[8] = pack2(a2.x, a2.x);  yp[9] = pack2(a2.y, a2.y);
            yp[10] = pack2(a2.z, a2.z); yp[11] = pack2(a2.w, a2.w);
            yp[12] = pack2(a3.x, a3.x); yp[13] = pack2(a3.y, a3.y);

            // weights for this i, pair block cg: ulonglong2 (16B) loads
            const ulonglong2* wr =
                reinterpret_cast<const ulonglong2*>(w2p) + i * 56 + cg * 2;
#pragma unroll
            for (int k = 0; k < 7; ++k) {
                ulonglong2 wA = wr[k * 8];
                ulonglong2 wB = wr[k * 8 + 1];
#pragma unroll
                for (int t = 0; t < 8; ++t) {
                    acc[0][t] = fma2(wA.x, yp[t + k], acc[0][t]);
                    acc[1][t] = fma2(wA.y, yp[t + k], acc[1][t]);
                    acc[2][t] = fma2(wB.x, yp[t + k], acc[2][t]);
                    acc[3][t] = fma2(wB.y, yp[t + k], acc[3][t]);
                }
            }
        }

        // epilogue: +bias, ReLU (max 0), pool over the 8 positions
        const ull* t2u = reinterpret_cast<const ull*>(t2p);
        const int pw = t0 / 40;
#pragma unroll
        for (int pp = 0; pp < 4; ++pp) {
            int pr = cg * 4 + pp;
            ull bi = t2u[pr];
            float mlo = 0.f, mhi = 0.f;
#pragma unroll
            for (int t = 0; t < 8; ++t) {
                float2 v = unpack2(add2(acc[pp][t], bi));
                mlo = fmaxf(mlo, v.x);
                mhi = fmaxf(mhi, v.y);
            }
            atomicMax(&pool_s[(2 * pr) * 10 + pw], __float_as_int(mlo));
            atomicMax(&pool_s[(2 * pr + 1) * 10 + pw], __float_as_int(mhi));
        }
    }
    __syncthreads();

    // ---------------- phase 3: write pooled features ----------------
    for (int idx = tid; idx < FEAT_PER_C; idx += 256)
        g_feat[b * NFEAT + c * FEAT_PER_C + idx] = __int_as_float(pool_s[idx]);
}

// =====================================================================
// Kernel B: FC1 outer-product, FFMA2, K-split partials
// grid (2 j-tiles of 64, KSPLIT), 256 threads; thread = 4b x 4j
// =====================================================================
__global__ __launch_bounds__(256) void fc1_kernel(const float* __restrict__ wc1)
{
    __shared__ __align__(16) float fs[64 * 66];
    __shared__ __align__(16) float ws[64 * 66];

    const int jt = blockIdx.x, ks = blockIdx.y;
    const int tid = threadIdx.x;
    const int bq = tid >> 4;        // 0..15 -> b rows {bq, bq+16, bq+32, bq+48}
    const int jq = tid & 15;        // 0..15 -> j rows {jq, jq+16, jq+32, jq+48}
    const int kbeg = ks * KCH, kend = kbeg + KCH;

    ull acc[4][4];
#pragma unroll
    for (int rb = 0; rb < 4; ++rb)
#pragma unroll
        for (int rj = 0; rj < 4; ++rj) acc[rb][rj] = 0ull;

    for (int k0 = kbeg; k0 < kend; k0 += 64) {
#pragma unroll
        for (int l = 0; l < 16; ++l) {
            int idx = tid + l * 256;
            int r = idx >> 6, cc = idx & 63;
            int k = k0 + cc;
            fs[r * 66 + cc] = (k < kend) ? g_feat[r * NFEAT + k] : 0.f;
            ws[r * 66 + cc] = (k < kend) ? wc1[(jt * 64 + r) * NFEAT + k] : 0.f;
        }
        __syncthreads();

        const ull* fs2 = reinterpret_cast<const ull*>(fs);
        const ull* ws2 = reinterpret_cast<const ull*>(ws);
#pragma unroll 4
        for (int cc2 = 0; cc2 < 32; ++cc2) {
            ull fv[4], wv[4];
#pragma unroll
            for (int r = 0; r < 4; ++r) fv[r] = fs2[(bq + 16 * r) * 33 + cc2];
#pragma unroll
            for (int r = 0; r < 4; ++r) wv[r] = ws2[(jq + 16 * r) * 33 + cc2];
#pragma unroll
            for (int rb = 0; rb < 4; ++rb)
#pragma unroll
                for (int rj = 0; rj < 4; ++rj)
                    acc[rb][rj] = fma2(fv[rb], wv[rj], acc[rb][rj]);
        }
        __syncthreads();
    }

#pragma unroll
    for (int rb = 0; rb < 4; ++rb) {
        int b = bq + 16 * rb;
#pragma unroll
        for (int rj = 0; rj < 4; ++rj) {
            int j = jt * 64 + jq + 16 * rj;
            float2 v = unpack2(acc[rb][rj]);
            g_part[(ks * NB + b) * 128 + j] = v.x + v.y;
        }
    }
}

// =====================================================================
// Kernel C: reduce partials, bias1, ReLU, FC2
// =====================================================================
__global__ __launch_bounds__(128) void fc2_kernel(
    const float* __restrict__ bc1, const float* __restrict__ wc2,
    const float* __restrict__ bc2, float* __restrict__ out)
{
    const int b = blockIdx.x, j = threadIdx.x;
    float s = bc1[j];
#pragma unroll 8
    for (int ks = 0; ks < KSPLIT; ++ks)
        s += g_part[(ks * NB + b) * 128 + j];
    float v = fmaxf(s, 0.f) * wc2[j];
#pragma unroll
    for (int o = 16; o > 0; o >>= 1)
        v += __shfl_down_sync(0xffffffffu, v, o);
    __shared__ float red[4];
    if ((j & 31) == 0) red[j >> 5] = v;
    __syncthreads();
    if (j == 0) out[b] = red[0] + red[1] + red[2] + red[3] + bc2[0];
}

// =====================================================================
extern "C" void kernel_launch(void* const* d_in, const int* in_sizes, int n_in,
                              void* d_out, int out_size)
{
    const float* x     = (const float*)d_in[0];
    const float* w1    = (const float*)d_in[1];
    const float* b1    = (const float*)d_in[2];
    const float* g1    = (const float*)d_in[3];
    const float* beta1 = (const float*)d_in[4];
    const float* m1    = (const float*)d_in[5];
    const float* v1    = (const float*)d_in[6];
    const float* w2    = (const float*)d_in[7];
    const float* b2    = (const float*)d_in[8];
    const float* g2    = (const float*)d_in[9];
    const float* beta2 = (const float*)d_in[10];
    const float* m2    = (const float*)d_in[11];
    const float* v2    = (const float*)d_in[12];
    const float* wc1   = (const float*)d_in[13];
    const float* bc1   = (const float*)d_in[14];
    const float* wc2   = (const float*)d_in[15];
    const float* bc2   = (const float*)d_in[16];
    float* out = (float*)d_out;

    prep_kernel<<<NC, 256>>>(w1, b1, g1, beta1, m1, v1,
                             w2, b2, g2, beta2, m2, v2);
    tower_kernel<<<NB * NC, 256>>>(x);
    fc1_kernel<<<dim3(2, KSPLIT), 256>>>(wc1);
    fc2_kernel<<<NB, 128>>>(bc1, wc2, bc2, out);
}

// round 8
// speedup vs baseline: 2.0816x; 1.0111x over previous
#include <cuda_runtime.h>
#include <cuda_bf16.h>

typedef unsigned long long ull;

#define NC 173
#define NL 400
#define NB 64
#define FEAT_PER_C 320          // 32 ch * 10 pool
#define NFEAT (NC * FEAT_PER_C) // 55360
#define KSPLIT 160
#define KCH (NFEAT / KSPLIT)    // 346

#define Y1S 416                 // y1 row stride (left halo 7, right pad)

__device__ float  g_feat[NB * NFEAT];          // pooled features [b][55360]
__device__ float  g_part[KSPLIT * NB * 128];   // FC1 partials [ks][b][j]
__device__ float  g_w1f[NC * 144];             // BN1-folded conv1 weights
__device__ float  g_t1 [NC * 16];              // BN1-folded bias
__device__ __align__(16) float2 g_w2i[NC * 1792]; // BN2-folded interleaved conv2 weights
__device__ float2 g_t2 [NC * 16];              // BN2-folded bias pairs

// ---------- packed f32x2 helpers (sm_103a FFMA2) ----------
__device__ __forceinline__ ull fma2(ull a, ull b, ull c) {
    ull d;
    asm("fma.rn.f32x2 %0, %1, %2, %3;" : "=l"(d) : "l"(a), "l"(b), "l"(c));
    return d;
}
__device__ __forceinline__ ull add2(ull a, ull b) {
    ull d;
    asm("add.rn.f32x2 %0, %1, %2;" : "=l"(d) : "l"(a), "l"(b));
    return d;
}
__device__ __forceinline__ ull pack2(float lo, float hi) {
    ull d;
    asm("mov.b64 %0, {%1, %2};" : "=l"(d) : "f"(lo), "f"(hi));
    return d;
}
__device__ __forceinline__ float2 unpack2(ull v) {
    float2 r;
    asm("mov.b64 {%0, %1}, %2;" : "=f"(r.x), "=f"(r.y) : "l"(v));
    return r;
}

// =====================================================================
// Kernel P: per-channel weight prep (BN fold + conv2 pair interleave)
// grid NC, 256 threads
// =====================================================================
__global__ __launch_bounds__(256) void prep_kernel(
    const float* __restrict__ w1g, const float* __restrict__ b1,
    const float* __restrict__ g1,  const float* __restrict__ beta1,
    const float* __restrict__ m1,  const float* __restrict__ v1,
    const float* __restrict__ w2g, const float* __restrict__ b2,
    const float* __restrict__ g2,  const float* __restrict__ beta2,
    const float* __restrict__ m2,  const float* __restrict__ v2)
{
    __shared__ float s1s[16], s2s[32], t2s[32];
    const int c = blockIdx.x, tid = threadIdx.x;

    if (tid < 16) {
        int cf = c * 16 + tid;
        float s = g1[cf] * rsqrtf(v1[cf] + 1e-5f);
        s1s[tid] = s;
        g_t1[cf] = s * (b1[cf] - m1[cf]) + beta1[cf];
    }
    if (tid >= 32 && tid < 64) {
        int o = tid - 32, co = c * 32 + o;
        float s = g2[co] * rsqrtf(v2[co] + 1e-5f);
        s2s[o] = s;
        t2s[o] = s * (b2[co] - m2[co]) + beta2[co];
    }
    __syncthreads();

    if (tid < 144)
        g_w1f[c * 144 + tid] = w1g[c * 144 + tid] * s1s[tid / 9];
    if (tid >= 144 && tid < 160) {
        int pr = tid - 144;
        g_t2[c * 16 + pr] = make_float2(t2s[2 * pr], t2s[2 * pr + 1]);
    }
    // interleave: g_w2i[c][(i*7+k)*16 + pr] = {s*w2[o=2pr], s*w2[o=2pr+1]}
    const float* wc = w2g + c * 3584;     // [o][i][k], o-stride 112
    for (int idx = tid; idx < 1792; idx += 256) {
        int pr = idx & 15, ik = idx >> 4;
        int i = ik / 7, k = ik - i * 7;
        int o0 = 2 * pr;
        g_w2i[c * 1792 + idx] = make_float2(wc[o0 * 112 + i * 7 + k] * s2s[o0],
                                            wc[(o0 + 1) * 112 + i * 7 + k] * s2s[o0 + 1]);
    }
}

// =====================================================================
// Kernel A: one block per (b, c), 320 threads.
// conv1 -> conv2 (FFMA2, T=10 pos x P=2 pairs per thread) -> pool
// =====================================================================
__global__ __launch_bounds__(320, 2) void tower_kernel(const float* __restrict__ x)
{
    __shared__ __align__(16) float xs[408];           // x with pad-4 halo
    __shared__ float w1s[144];                        // folded 16x9
    __shared__ float t1s[16];
    __shared__ __align__(16) float y1s[16 * Y1S];     // conv1 out, halo-7 left
    __shared__ __align__(16) float2 w2p[16 * 7 * 16]; // [i][k][opair]
    __shared__ float2 t2p[16];
    __shared__ int pool_s[FEAT_PER_C];

    const int bc = blockIdx.x;
    const int b = bc / NC, c = bc - b * NC;
    const int tid = threadIdx.x;

    // ---------------- phase 0: coalesced staging ----------------
    const float* xrow = x + bc * NL;
    for (int idx = tid; idx < 408; idx += 320)
        xs[idx] = (idx >= 4 && idx < 404) ? xrow[idx - 4] : 0.f;
    if (tid < 144) w1s[tid] = g_w1f[c * 144 + tid];
    if (tid >= 144 && tid < 160) t1s[tid - 144] = g_t1[c * 16 + tid - 144];
    if (tid >= 160 && tid < 176) t2p[tid - 160] = g_t2[c * 16 + tid - 160];
    {   // w2p copy: 1792 float2 = 896 float4
        const float4* src = reinterpret_cast<const float4*>(g_w2i + c * 1792);
        float4* dst = reinterpret_cast<float4*>(w2p);
        for (int idx = tid; idx < 896; idx += 320) dst[idx] = src[idx];
    }
    if (tid < 256) {     // zero y1 halos: cols 0..6 and 407..415 (16 per row)
        int i = tid >> 4, jj = tid & 15;
        y1s[i * Y1S + (jj < 7 ? jj : 400 + jj)] = 0.f;
    }
    if (tid >= 256 && tid < 256 + 64) pool_s[256 + (tid - 256)] = 0;
    if (tid < 256) pool_s[tid] = 0;
    __syncthreads();

    // ---------------- phase 1: conv1 (16 x 400) + bias + ReLU ----------------
    for (int idx = tid; idx < 6400; idx += 320) {
        int f = idx / 400, t = idx - f * 400;
        const float* wf = &w1s[f * 9];
        float a = 0.f;
#pragma unroll
        for (int k = 0; k < 9; ++k) a = fmaf(wf[k], xs[t + k], a);
        y1s[f * Y1S + 7 + t] = fmaxf(a + t1s[f], 0.f);
    }
    __syncthreads();

    // ------ phase 2: conv2 (32 x 400) FFMA2 + bias + ReLU + pool ------
    // thread = (g, cg): g = tid>>3 (position tile of 10), cg = tid&7 (pair pair)
    {
        const int g  = tid >> 3;       // 0..39
        const int cg = tid & 7;        // pairs {2cg, 2cg+1} -> channels 4cg..4cg+3
        const int t0 = g * 10;

        ull acc[2][10];
#pragma unroll
        for (int p = 0; p < 2; ++p)
#pragma unroll
            for (int t = 0; t < 10; ++t) acc[p][t] = 0ull;

        const ulonglong2* w2u2 = reinterpret_cast<const ulonglong2*>(w2p);

#pragma unroll 1
        for (int i = 0; i < 16; ++i) {
            // 16-float window, 8B aligned: cols t0+4 .. t0+19 (t = t0-3..t0+12)
            const float2* ybase =
                reinterpret_cast<const float2*>(&y1s[i * Y1S + t0 + 4]);
            ull yp[16];
#pragma unroll
            for (int m = 0; m < 8; ++m) {
                float2 a = ybase[m];
                yp[2 * m]     = pack2(a.x, a.x);
                yp[2 * m + 1] = pack2(a.y, a.y);
            }
            const ulonglong2* wr = w2u2 + i * 56 + cg;   // stride 8 per k
#pragma unroll
            for (int k = 0; k < 7; ++k) {
                ulonglong2 w = wr[k * 8];
#pragma unroll
                for (int t = 0; t < 10; ++t) {
                    acc[0][t] = fma2(w.x, yp[t + k], acc[0][t]);
                    acc[1][t] = fma2(w.y, yp[t + k], acc[1][t]);
                }
            }
        }

        // epilogue: +bias, ReLU (max 0), pool the 10 positions (one window)
        const ull* t2u = reinterpret_cast<const ull*>(t2p);
        const int pw = g >> 2;                 // t0/40
#pragma unroll
        for (int p = 0; p < 2; ++p) {
            int pr = 2 * cg + p;
            ull bi = t2u[pr];
            float mlo = 0.f, mhi = 0.f;
#pragma unroll
            for (int t = 0; t < 10; ++t) {
                float2 v = unpack2(add2(acc[p][t], bi));
                mlo = fmaxf(mlo, v.x);
                mhi = fmaxf(mhi, v.y);
            }
            atomicMax(&pool_s[(2 * pr) * 10 + pw], __float_as_int(mlo));
            atomicMax(&pool_s[(2 * pr + 1) * 10 + pw], __float_as_int(mhi));
        }
    }
    __syncthreads();

    // ---------------- phase 3: write pooled features ----------------
    if (tid < FEAT_PER_C)
        g_feat[b * NFEAT + c * FEAT_PER_C + tid] = __int_as_float(pool_s[tid]);
}

// =====================================================================
// Kernel B: FC1 outer-product, FFMA2, K-split partials
// grid (2 j-tiles of 64, KSPLIT), 256 threads; thread = 4b x 4j
// =====================================================================
__global__ __launch_bounds__(256) void fc1_kernel(const float* __restrict__ wc1)
{
    __shared__ __align__(16) float fs[64 * 66];
    __shared__ __align__(16) float ws[64 * 66];

    const int jt = blockIdx.x, ks = blockIdx.y;
    const int tid = threadIdx.x;
    const int bq = tid >> 4;        // 0..15 -> b rows {bq, bq+16, bq+32, bq+48}
    const int jq = tid & 15;        // 0..15 -> j rows {jq, jq+16, jq+32, jq+48}
    const int kbeg = ks * KCH, kend = kbeg + KCH;

    ull acc[4][4];
#pragma unroll
    for (int rb = 0; rb < 4; ++rb)
#pragma unroll
        for (int rj = 0; rj < 4; ++rj) acc[rb][rj] = 0ull;

    for (int k0 = kbeg; k0 < kend; k0 += 64) {
#pragma unroll
        for (int l = 0; l < 16; ++l) {
            int idx = tid + l * 256;
            int r = idx >> 6, cc = idx & 63;
            int k = k0 + cc;
            fs[r * 66 + cc] = (k < kend) ? g_feat[r * NFEAT + k] : 0.f;
            ws[r * 66 + cc] = (k < kend) ? wc1[(jt * 64 + r) * NFEAT + k] : 0.f;
        }
        __syncthreads();

        const ull* fs2 = reinterpret_cast<const ull*>(fs);
        const ull* ws2 = reinterpret_cast<const ull*>(ws);
#pragma unroll 4
        for (int cc2 = 0; cc2 < 32; ++cc2) {
            ull fv[4], wv[4];
#pragma unroll
            for (int r = 0; r < 4; ++r) fv[r] = fs2[(bq + 16 * r) * 33 + cc2];
#pragma unroll
            for (int r = 0; r < 4; ++r) wv[r] = ws2[(jq + 16 * r) * 33 + cc2];
#pragma unroll
            for (int rb = 0; rb < 4; ++rb)
#pragma unroll
                for (int rj = 0; rj < 4; ++rj)
                    acc[rb][rj] = fma2(fv[rb], wv[rj], acc[rb][rj]);
        }
        __syncthreads();
    }

#pragma unroll
    for (int rb = 0; rb < 4; ++rb) {
        int b = bq + 16 * rb;
#pragma unroll
        for (int rj = 0; rj < 4; ++rj) {
            int j = jt * 64 + jq + 16 * rj;
            float2 v = unpack2(acc[rb][rj]);
            g_part[(ks * NB + b) * 128 + j] = v.x + v.y;
        }
    }
}

// =====================================================================
// Kernel C: reduce partials (8-way split), bias1, ReLU, FC2
// grid 64 (batch), 1024 threads
// =====================================================================
__global__ __launch_bounds__(1024) void fc2_kernel(
    const float* __restrict__ bc1, const float* __restrict__ wc2,
    const float* __restrict__ bc2, float* __restrict__ out)
{
    __shared__ float part[8][128];
    __shared__ float red[4];
    const int b = blockIdx.x;
    const int j = threadIdx.x & 127, r = threadIdx.x >> 7;   // r 0..7

    float s = 0.f;
#pragma unroll 5
    for (int ks = r; ks < KSPLIT; ks += 8)
        s += g_part[(ks * NB + b) * 128 + j];
    part[r][j] = s;
    __syncthreads();

    if (threadIdx.x < 128) {
        float t = bc1[j];
#pragma unroll
        for (int r2 = 0; r2 < 8; ++r2) t += part[r2][j];
        float v = fmaxf(t, 0.f) * wc2[j];
#pragma unroll
        for (int o = 16; o > 0; o >>= 1)
            v += __shfl_down_sync(0xffffffffu, v, o);
        if ((j & 31) == 0) red[j >> 5] = v;
    }
    __syncthreads();
    if (threadIdx.x == 0) out[b] = red[0] + red[1] + red[2] + red[3] + bc2[0];
}

// =====================================================================
extern "C" void kernel_launch(void* const* d_in, const int* in_sizes, int n_in,
                              void* d_out, int out_size)
{
    const float* x     = (const float*)d_in[0];
    const float* w1    = (const float*)d_in[1];
    const float* b1    = (const float*)d_in[2];
    const float* g1    = (const float*)d_in[3];
    const float* beta1 = (const float*)d_in[4];
    const float* m1    = (const float*)d_in[5];
    const float* v1    = (const float*)d_in[6];
    const float* w2    = (const float*)d_in[7];
    const float* b2    = (const float*)d_in[8];
    const float* g2    = (const float*)d_in[9];
    const float* beta2 = (const float*)d_in[10];
    const float* v2    = (const float*)d_in[12];
    const float* m2    = (const float*)d_in[11];
    const float* wc1   = (const float*)d_in[13];
    const float* bc1   = (const float*)d_in[14];
    const float* wc2   = (const float*)d_in[15];
    const float* bc2   = (const float*)d_in[16];
    float* out = (float*)d_out;

    prep_kernel<<<NC, 256>>>(w1, b1, g1, beta1, m1, v1,
                             w2, b2, g2, beta2, m2, v2);
    tower_kernel<<<NB * NC, 320>>>(x);
    fc1_kernel<<<dim3(2, KSPLIT), 256>>>(wc1);
    fc2_kernel<<<NB, 1024>>>(bc1, wc2, bc2, out);
}

// round 9
// speedup vs baseline: 2.1914x; 1.0527x over previous
#include <cuda_runtime.h>
#include <cuda_bf16.h>

typedef unsigned long long ull;

#define NC 173
#define NL 400
#define NB 64
#define FEAT_PER_C 320          // 32 ch * 10 pool
#define NFEAT (NC * FEAT_PER_C) // 55360
#define KSPLIT 160
#define KCH (NFEAT / KSPLIT)    // 346

#define Y1S 416                 // y1 row stride (left halo 7, right pad)

__device__ float  g_feat[NB * NFEAT];          // pooled features [b][55360]
__device__ float  g_part[KSPLIT * NB * 128];   // FC1 partials [ks][b][j]
__device__ float  g_w1f[NC * 144];             // BN1-folded conv1 weights
__device__ float  g_t1 [NC * 16];              // BN1-folded bias
__device__ __align__(16) float2 g_w2i[NC * 1792]; // BN2-folded interleaved conv2 weights
__device__ float2 g_t2 [NC * 16];              // BN2-folded bias pairs

// ---------- packed f32x2 helpers (sm_103a FFMA2) ----------
__device__ __forceinline__ ull fma2(ull a, ull b, ull c) {
    ull d;
    asm("fma.rn.f32x2 %0, %1, %2, %3;" : "=l"(d) : "l"(a), "l"(b), "l"(c));
    return d;
}
__device__ __forceinline__ ull add2(ull a, ull b) {
    ull d;
    asm("add.rn.f32x2 %0, %1, %2;" : "=l"(d) : "l"(a), "l"(b));
    return d;
}
__device__ __forceinline__ ull pack2(float lo, float hi) {
    ull d;
    asm("mov.b64 %0, {%1, %2};" : "=l"(d) : "f"(lo), "f"(hi));
    return d;
}
__device__ __forceinline__ float2 unpack2(ull v) {
    float2 r;
    asm("mov.b64 {%0, %1}, %2;" : "=f"(r.x), "=f"(r.y) : "l"(v));
    return r;
}

// =====================================================================
// Kernel P: per-channel weight prep (BN fold + conv2 pair interleave)
// =====================================================================
__global__ __launch_bounds__(256) void prep_kernel(
    const float* __restrict__ w1g, const float* __restrict__ b1,
    const float* __restrict__ g1,  const float* __restrict__ beta1,
    const float* __restrict__ m1,  const float* __restrict__ v1,
    const float* __restrict__ w2g, const float* __restrict__ b2,
    const float* __restrict__ g2,  const float* __restrict__ beta2,
    const float* __restrict__ m2,  const float* __restrict__ v2)
{
    __shared__ float s1s[16], s2s[32], t2s[32];
    const int c = blockIdx.x, tid = threadIdx.x;

    if (tid < 16) {
        int cf = c * 16 + tid;
        float s = g1[cf] * rsqrtf(v1[cf] + 1e-5f);
        s1s[tid] = s;
        g_t1[cf] = s * (b1[cf] - m1[cf]) + beta1[cf];
    }
    if (tid >= 32 && tid < 64) {
        int o = tid - 32, co = c * 32 + o;
        float s = g2[co] * rsqrtf(v2[co] + 1e-5f);
        s2s[o] = s;
        t2s[o] = s * (b2[co] - m2[co]) + beta2[co];
    }
    __syncthreads();

    if (tid < 144)
        g_w1f[c * 144 + tid] = w1g[c * 144 + tid] * s1s[tid / 9];
    if (tid >= 144 && tid < 160) {
        int pr = tid - 144;
        g_t2[c * 16 + pr] = make_float2(t2s[2 * pr], t2s[2 * pr + 1]);
    }
    // interleave: g_w2i[c][(i*7+k)*16 + pr] = {s*w2[o=2pr], s*w2[o=2pr+1]}
    const float* wc = w2g + c * 3584;     // [o][i][k], o-stride 112
    for (int idx = tid; idx < 1792; idx += 256) {
        int pr = idx & 15, ik = idx >> 4;
        int i = ik / 7, k = ik - i * 7;
        int o0 = 2 * pr;
        g_w2i[c * 1792 + idx] = make_float2(wc[o0 * 112 + i * 7 + k] * s2s[o0],
                                            wc[(o0 + 1) * 112 + i * 7 + k] * s2s[o0 + 1]);
    }
}

// =====================================================================
// Kernel A: one block per (b, c), 320 threads.
// conv1 -> conv2 (FFMA2, T=10 pos x P=2 pairs per thread) -> pool
// Pooling via disjoint smem partial slots (NO atomics).
// =====================================================================
__global__ __launch_bounds__(320, 2) void tower_kernel(const float* __restrict__ x)
{
    __shared__ __align__(16) float xs[408];           // x with pad-4 halo
    __shared__ float w1s[144];                        // folded 16x9
    __shared__ float t1s[16];
    __shared__ __align__(16) float y1s[16 * Y1S];     // conv1 out, halo-7 left
    __shared__ __align__(16) float2 w2p[16 * 7 * 16]; // [i][k][opair]
    __shared__ float2 t2p[16];
    __shared__ __align__(16) float4 pool_p[FEAT_PER_C]; // [ch*10+pw] x 4 subs

    const int bc = blockIdx.x;
    const int b = bc / NC, c = bc - b * NC;
    const int tid = threadIdx.x;

    // ---------------- phase 0: coalesced staging ----------------
    const float* xrow = x + bc * NL;
    for (int idx = tid; idx < 408; idx += 320)
        xs[idx] = (idx >= 4 && idx < 404) ? xrow[idx - 4] : 0.f;
    if (tid < 144) w1s[tid] = g_w1f[c * 144 + tid];
    if (tid >= 144 && tid < 160) t1s[tid - 144] = g_t1[c * 16 + tid - 144];
    if (tid >= 160 && tid < 176) t2p[tid - 160] = g_t2[c * 16 + tid - 160];
    {   // w2p copy: 1792 float2 = 896 float4
        const float4* src = reinterpret_cast<const float4*>(g_w2i + c * 1792);
        float4* dst = reinterpret_cast<float4*>(w2p);
        for (int idx = tid; idx < 896; idx += 320) dst[idx] = src[idx];
    }
    if (tid < 256) {     // zero y1 halos: cols 0..6 and 407..415 (16 per row)
        int i = tid >> 4, jj = tid & 15;
        y1s[i * Y1S + (jj < 7 ? jj : 400 + jj)] = 0.f;
    }
    __syncthreads();

    // ---------------- phase 1: conv1 (16 x 400) + bias + ReLU ----------------
    for (int idx = tid; idx < 6400; idx += 320) {
        int f = idx / 400, t = idx - f * 400;
        const float* wf = &w1s[f * 9];
        float a = 0.f;
#pragma unroll
        for (int k = 0; k < 9; ++k) a = fmaf(wf[k], xs[t + k], a);
        y1s[f * Y1S + 7 + t] = fmaxf(a + t1s[f], 0.f);
    }
    __syncthreads();

    // ------ phase 2: conv2 (32 x 400) FFMA2 + bias + ReLU + pool partials ------
    // thread = (g, cg): g = tid>>3 (position tile of 10), cg = tid&7 (pair pair)
    {
        const int g  = tid >> 3;       // 0..39
        const int cg = tid & 7;        // pairs {2cg, 2cg+1} -> channels 4cg..4cg+3
        const int t0 = g * 10;

        ull acc[2][10];
#pragma unroll
        for (int p = 0; p < 2; ++p)
#pragma unroll
            for (int t = 0; t < 10; ++t) acc[p][t] = 0ull;

        const ulonglong2* w2u2 = reinterpret_cast<const ulonglong2*>(w2p);

#pragma unroll 1
        for (int i = 0; i < 16; ++i) {
            // 16-float window, 8B aligned: cols t0+4 .. t0+19 (t = t0-3..t0+12)
            const float2* ybase =
                reinterpret_cast<const float2*>(&y1s[i * Y1S + t0 + 4]);
            ull yp[16];
#pragma unroll
            for (int m = 0; m < 8; ++m) {
                float2 a = ybase[m];
                yp[2 * m]     = pack2(a.x, a.x);
                yp[2 * m + 1] = pack2(a.y, a.y);
            }
            const ulonglong2* wr = w2u2 + i * 56 + cg;   // stride 8 per k
#pragma unroll
            for (int k = 0; k < 7; ++k) {
                ulonglong2 w = wr[k * 8];
#pragma unroll
                for (int t = 0; t < 10; ++t) {
                    acc[0][t] = fma2(w.x, yp[t + k], acc[0][t]);
                    acc[1][t] = fma2(w.y, yp[t + k], acc[1][t]);
                }
            }
        }

        // epilogue: +bias, ReLU (max 0), pool the 10 positions, scatter partial
        const ull* t2u = reinterpret_cast<const ull*>(t2p);
        const int pw = g >> 2;                 // window index t0/40
        const int sub = g & 3;                 // sub-slot within window
        float* poolf = reinterpret_cast<float*>(pool_p);
#pragma unroll
        for (int p = 0; p < 2; ++p) {
            int pr = 2 * cg + p;
            ull bi = t2u[pr];
            float mlo = 0.f, mhi = 0.f;
#pragma unroll
            for (int t = 0; t < 10; ++t) {
                float2 v = unpack2(add2(acc[p][t], bi));
                mlo = fmaxf(mlo, v.x);
                mhi = fmaxf(mhi, v.y);
            }
            poolf[((2 * pr) * 10 + pw) * 4 + sub]     = mlo;
            poolf[((2 * pr + 1) * 10 + pw) * 4 + sub] = mhi;
        }
    }
    __syncthreads();

    // ---------------- phase 3: reduce 4 partials, write features ----------------
    if (tid < FEAT_PER_C) {
        float4 v = pool_p[tid];
        g_feat[b * NFEAT + c * FEAT_PER_C + tid] =
            fmaxf(fmaxf(v.x, v.y), fmaxf(v.z, v.w));
    }
}

// =====================================================================
// Kernel B: FC1 outer-product, FFMA2, K-split partials
// grid (2 j-tiles of 64, KSPLIT), 256 threads; thread = 4b x 4j
// =====================================================================
__global__ __launch_bounds__(256) void fc1_kernel(const float* __restrict__ wc1)
{
    __shared__ __align__(16) float fs[64 * 66];
    __shared__ __align__(16) float ws[64 * 66];

    const int jt = blockIdx.x, ks = blockIdx.y;
    const int tid = threadIdx.x;
    const int bq = tid >> 4;        // 0..15 -> b rows {bq, bq+16, bq+32, bq+48}
    const int jq = tid & 15;        // 0..15 -> j rows {jq, jq+16, jq+32, jq+48}
    const int kbeg = ks * KCH, kend = kbeg + KCH;

    ull acc[4][4];
#pragma unroll
    for (int rb = 0; rb < 4; ++rb)
#pragma unroll
        for (int rj = 0; rj < 4; ++rj) acc[rb][rj] = 0ull;

    for (int k0 = kbeg; k0 < kend; k0 += 64) {
#pragma unroll
        for (int l = 0; l < 16; ++l) {
            int idx = tid + l * 256;
            int r = idx >> 6, cc = idx & 63;
            int k = k0 + cc;
            fs[r * 66 + cc] = (k < kend) ? g_feat[r * NFEAT + k] : 0.f;
            ws[r * 66 + cc] = (k < kend) ? wc1[(jt * 64 + r) * NFEAT + k] : 0.f;
        }
        __syncthreads();

        const ull* fs2 = reinterpret_cast<const ull*>(fs);
        const ull* ws2 = reinterpret_cast<const ull*>(ws);
#pragma unroll 4
        for (int cc2 = 0; cc2 < 32; ++cc2) {
            ull fv[4], wv[4];
#pragma unroll
            for (int r = 0; r < 4; ++r) fv[r] = fs2[(bq + 16 * r) * 33 + cc2];
#pragma unroll
            for (int r = 0; r < 4; ++r) wv[r] = ws2[(jq + 16 * r) * 33 + cc2];
#pragma unroll
            for (int rb = 0; rb < 4; ++rb)
#pragma unroll
                for (int rj = 0; rj < 4; ++rj)
                    acc[rb][rj] = fma2(fv[rb], wv[rj], acc[rb][rj]);
        }
        __syncthreads();
    }

#pragma unroll
    for (int rb = 0; rb < 4; ++rb) {
        int b = bq + 16 * rb;
#pragma unroll
        for (int rj = 0; rj < 4; ++rj) {
            int j = jt * 64 + jq + 16 * rj;
            float2 v = unpack2(acc[rb][rj]);
            g_part[(ks * NB + b) * 128 + j] = v.x + v.y;
        }
    }
}

// =====================================================================
// Kernel C: reduce partials (8-way split), bias1, ReLU, FC2
// =====================================================================
__global__ __launch_bounds__(1024) void fc2_kernel(
    const float* __restrict__ bc1, const float* __restrict__ wc2,
    const float* __restrict__ bc2, float* __restrict__ out)
{
    __shared__ float part[8][128];
    __shared__ float red[4];
    const int b = blockIdx.x;
    const int j = threadIdx.x & 127, r = threadIdx.x >> 7;   // r 0..7

    float s = 0.f;
#pragma unroll 5
    for (int ks = r; ks < KSPLIT; ks += 8)
        s += g_part[(ks * NB + b) * 128 + j];
    part[r][j] = s;
    __syncthreads();

    if (threadIdx.x < 128) {
        float t = bc1[j];
#pragma unroll
        for (int r2 = 0; r2 < 8; ++r2) t += part[r2][j];
        float v = fmaxf(t, 0.f) * wc2[j];
#pragma unroll
        for (int o = 16; o > 0; o >>= 1)
            v += __shfl_down_sync(0xffffffffu, v, o);
        if ((j & 31) == 0) red[j >> 5] = v;
    }
    __syncthreads();
    if (threadIdx.x == 0) out[b] = red[0] + red[1] + red[2] + red[3] + bc2[0];
}

// =====================================================================
extern "C" void kernel_launch(void* const* d_in, const int* in_sizes, int n_in,
                              void* d_out, int out_size)
{
    const float* x     = (const float*)d_in[0];
    const float* w1    = (const float*)d_in[1];
    const float* b1    = (const float*)d_in[2];
    const float* g1    = (const float*)d_in[3];
    const float* beta1 = (const float*)d_in[4];
    const float* m1    = (const float*)d_in[5];
    const float* v1    = (const float*)d_in[6];
    const float* w2    = (const float*)d_in[7];
    const float* b2    = (const float*)d_in[8];
    const float* g2    = (const float*)d_in[9];
    const float* beta2 = (const float*)d_in[10];
    const float* m2    = (const float*)d_in[11];
    const float* v2    = (const float*)d_in[12];
    const float* wc1   = (const float*)d_in[13];
    const float* bc1   = (const float*)d_in[14];
    const float* wc2   = (const float*)d_in[15];
    const float* bc2   = (const float*)d_in[16];
    float* out = (float*)d_out;

    prep_kernel<<<NC, 256>>>(w1, b1, g1, beta1, m1, v1,
                             w2, b2, g2, beta2, m2, v2);
    tower_kernel<<<NB * NC, 320>>>(x);
    fc1_kernel<<<dim3(2, KSPLIT), 256>>>(wc1);
    fc2_kernel<<<NB, 1024>>>(bc1, wc2, bc2, out);
}

// round 10
// speedup vs baseline: 2.2226x; 1.0143x over previous
#include <cuda_runtime.h>
#include <cuda_bf16.h>

typedef unsigned long long ull;

#define NC 173
#define NL 400
#define NB 64
#define BPB 4                   // batches per tower block
#define FEAT_PER_C 320          // 32 ch * 10 pool
#define NFEAT (NC * FEAT_PER_C) // 55360
#define KSPLIT 160
#define KCH (NFEAT / KSPLIT)    // 346

#define Y1S 416                 // y1 row stride (left halo 7, right pad)
#define XSS 416                 // xs row stride

__device__ float  g_feat[NB * NFEAT];          // pooled features [b][55360]
__device__ float  g_part[KSPLIT * NB * 128];   // FC1 partials [ks][b][j]
__device__ float  g_w1f[NC * 144];             // BN1-folded conv1 weights
__device__ float  g_t1 [NC * 16];              // BN1-folded bias
__device__ __align__(16) float2 g_w2i[NC * 1792]; // BN2-folded interleaved conv2 weights
__device__ float2 g_t2 [NC * 16];              // BN2-folded bias pairs

// ---------- packed f32x2 helpers (sm_103a FFMA2) ----------
__device__ __forceinline__ ull fma2(ull a, ull b, ull c) {
    ull d;
    asm("fma.rn.f32x2 %0, %1, %2, %3;" : "=l"(d) : "l"(a), "l"(b), "l"(c));
    return d;
}
__device__ __forceinline__ ull add2(ull a, ull b) {
    ull d;
    asm("add.rn.f32x2 %0, %1, %2;" : "=l"(d) : "l"(a), "l"(b));
    return d;
}
__device__ __forceinline__ ull pack2(float lo, float hi) {
    ull d;
    asm("mov.b64 %0, {%1, %2};" : "=l"(d) : "f"(lo), "f"(hi));
    return d;
}
__device__ __forceinline__ float2 unpack2(ull v) {
    float2 r;
    asm("mov.b64 {%0, %1}, %2;" : "=f"(r.x), "=f"(r.y) : "l"(v));
    return r;
}

// =====================================================================
// Kernel P: per-channel weight prep (BN fold + conv2 pair interleave)
// =====================================================================
__global__ __launch_bounds__(256) void prep_kernel(
    const float* __restrict__ w1g, const float* __restrict__ b1,
    const float* __restrict__ g1,  const float* __restrict__ beta1,
    const float* __restrict__ m1,  const float* __restrict__ v1,
    const float* __restrict__ w2g, const float* __restrict__ b2,
    const float* __restrict__ g2,  const float* __restrict__ beta2,
    const float* __restrict__ m2,  const float* __restrict__ v2)
{
    __shared__ float s1s[16], s2s[32], t2s[32];
    const int c = blockIdx.x, tid = threadIdx.x;

    if (tid < 16) {
        int cf = c * 16 + tid;
        float s = g1[cf] * rsqrtf(v1[cf] + 1e-5f);
        s1s[tid] = s;
        g_t1[cf] = s * (b1[cf] - m1[cf]) + beta1[cf];
    }
    if (tid >= 32 && tid < 64) {
        int o = tid - 32, co = c * 32 + o;
        float s = g2[co] * rsqrtf(v2[co] + 1e-5f);
        s2s[o] = s;
        t2s[o] = s * (b2[co] - m2[co]) + beta2[co];
    }
    __syncthreads();

    if (tid < 144)
        g_w1f[c * 144 + tid] = w1g[c * 144 + tid] * s1s[tid / 9];
    if (tid >= 144 && tid < 160) {
        int pr = tid - 144;
        g_t2[c * 16 + pr] = make_float2(t2s[2 * pr], t2s[2 * pr + 1]);
    }
    // interleave: g_w2i[c][(i*7+k)*16 + pr] = {s*w2[o=2pr], s*w2[o=2pr+1]}
    const float* wc = w2g + c * 3584;     // [o][i][k], o-stride 112
    for (int idx = tid; idx < 1792; idx += 256) {
        int pr = idx & 15, ik = idx >> 4;
        int i = ik / 7, k = ik - i * 7;
        int o0 = 2 * pr;
        g_w2i[c * 1792 + idx] = make_float2(wc[o0 * 112 + i * 7 + k] * s2s[o0],
                                            wc[(o0 + 1) * 112 + i * 7 + k] * s2s[o0 + 1]);
    }
}

// =====================================================================
// Kernel A: one block per (c, 4 batches), 320 threads.
// Stage weights once; loop 4 batches: conv1 -> conv2 (FFMA2) -> pool.
// =====================================================================
__global__ __launch_bounds__(320, 2) void tower_kernel(const float* __restrict__ x)
{
    __shared__ __align__(16) float xs[BPB * XSS];     // 4 x rows, pad-4 halo
    __shared__ float w1s[144];                        // folded 16x9
    __shared__ float t1s[16];
    __shared__ __align__(16) float y1s[16 * Y1S];     // conv1 out, halo-7 left
    __shared__ __align__(16) float2 w2p[16 * 7 * 16]; // [i][k][opair]
    __shared__ float2 t2p[16];
    __shared__ __align__(16) float4 pool_p[FEAT_PER_C]; // [ch*10+pw] x 4 subs

    const int blk = blockIdx.x;
    const int bg = blk / NC, c = blk - bg * NC;
    const int b0 = bg * BPB;
    const int tid = threadIdx.x;

    // ---------------- phase 0: stage once per block ----------------
    for (int idx = tid; idx < BPB * 408; idx += 320) {
        int r = idx / 408, j = idx - r * 408;
        xs[r * XSS + j] = (j >= 4 && j < 404)
                        ? x[((b0 + r) * NC + c) * NL + (j - 4)] : 0.f;
    }
    if (tid < 144) w1s[tid] = g_w1f[c * 144 + tid];
    if (tid >= 144 && tid < 160) t1s[tid - 144] = g_t1[c * 16 + tid - 144];
    if (tid >= 160 && tid < 176) t2p[tid - 160] = g_t2[c * 16 + tid - 160];
    {   // w2p copy: 1792 float2 = 896 float4
        const float4* src = reinterpret_cast<const float4*>(g_w2i + c * 1792);
        float4* dst = reinterpret_cast<float4*>(w2p);
        for (int idx = tid; idx < 896; idx += 320) dst[idx] = src[idx];
    }
    if (tid < 256) {     // zero y1 halos once (never overwritten)
        int i = tid >> 4, jj = tid & 15;
        y1s[i * Y1S + (jj < 7 ? jj : 400 + jj)] = 0.f;
    }
    __syncthreads();

    // ---------------- conv1 for batch 0 ----------------
    {
        const float* xb = &xs[0];
        for (int idx = tid; idx < 6400; idx += 320) {
            int f = idx / 400, t = idx - f * 400;
            const float* wf = &w1s[f * 9];
            float a = 0.f;
#pragma unroll
            for (int k = 0; k < 9; ++k) a = fmaf(wf[k], xb[t + k], a);
            y1s[f * Y1S + 7 + t] = fmaxf(a + t1s[f], 0.f);
        }
    }
    __syncthreads();

#pragma unroll 1
    for (int bb = 0; bb < BPB; ++bb) {
        // ---- conv2 (32 x 400) FFMA2 + bias + ReLU + pool partials ----
        {
            const int g  = tid >> 3;       // 0..39: position tile of 10
            const int cg = tid & 7;        // pairs {2cg,2cg+1} -> ch 4cg..4cg+3
            const int t0 = g * 10;

            ull acc[2][10];
#pragma unroll
            for (int p = 0; p < 2; ++p)
#pragma unroll
                for (int t = 0; t < 10; ++t) acc[p][t] = 0ull;

            const ulonglong2* w2u2 = reinterpret_cast<const ulonglong2*>(w2p);

#pragma unroll 1
            for (int i = 0; i < 16; ++i) {
                const float2* ybase =
                    reinterpret_cast<const float2*>(&y1s[i * Y1S + t0 + 4]);
                ull yp[16];
#pragma unroll
                for (int m = 0; m < 8; ++m) {
                    float2 a = ybase[m];
                    yp[2 * m]     = pack2(a.x, a.x);
                    yp[2 * m + 1] = pack2(a.y, a.y);
                }
                const ulonglong2* wr = w2u2 + i * 56 + cg;   // stride 8 per k
#pragma unroll
                for (int k = 0; k < 7; ++k) {
                    ulonglong2 w = wr[k * 8];
#pragma unroll
                    for (int t = 0; t < 10; ++t) {
                        acc[0][t] = fma2(w.x, yp[t + k], acc[0][t]);
                        acc[1][t] = fma2(w.y, yp[t + k], acc[1][t]);
                    }
                }
            }

            // epilogue: +bias, ReLU, pool 10 positions, scatter partial
            const ull* t2u = reinterpret_cast<const ull*>(t2p);
            const int pw = g >> 2;
            const int sub = g & 3;
            float* poolf = reinterpret_cast<float*>(pool_p);
#pragma unroll
            for (int p = 0; p < 2; ++p) {
                int pr = 2 * cg + p;
                ull bi = t2u[pr];
                float mlo = 0.f, mhi = 0.f;
#pragma unroll
                for (int t = 0; t < 10; ++t) {
                    float2 v = unpack2(add2(acc[p][t], bi));
                    mlo = fmaxf(mlo, v.x);
                    mhi = fmaxf(mhi, v.y);
                }
                poolf[((2 * pr) * 10 + pw) * 4 + sub]     = mlo;
                poolf[((2 * pr + 1) * 10 + pw) * 4 + sub] = mhi;
            }
        }
        __syncthreads();

        // ---- writeback(bb) + conv1(bb+1) between the same pair of syncs ----
        {
            float4 v = pool_p[tid];               // FEAT_PER_C == blockDim == 320
            g_feat[(b0 + bb) * NFEAT + c * FEAT_PER_C + tid] =
                fmaxf(fmaxf(v.x, v.y), fmaxf(v.z, v.w));
        }
        if (bb + 1 < BPB) {
            const float* xb = &xs[(bb + 1) * XSS];
            for (int idx = tid; idx < 6400; idx += 320) {
                int f = idx / 400, t = idx - f * 400;
                const float* wf = &w1s[f * 9];
                float a = 0.f;
#pragma unroll
                for (int k = 0; k < 9; ++k) a = fmaf(wf[k], xb[t + k], a);
                y1s[f * Y1S + 7 + t] = fmaxf(a + t1s[f], 0.f);
            }
            __syncthreads();
        }
    }
}

// =====================================================================
// Kernel B: FC1 outer-product, FFMA2, K-split partials
// grid (2 j-tiles of 64, KSPLIT), 256 threads; thread = 4b x 4j
// =====================================================================
__global__ __launch_bounds__(256) void fc1_kernel(const float* __restrict__ wc1)
{
    __shared__ __align__(16) float fs[64 * 66];
    __shared__ __align__(16) float ws[64 * 66];

    const int jt = blockIdx.x, ks = blockIdx.y;
    const int tid = threadIdx.x;
    const int bq = tid >> 4;        // 0..15 -> b rows {bq, bq+16, bq+32, bq+48}
    const int jq = tid & 15;        // 0..15 -> j rows {jq, jq+16, jq+32, jq+48}
    const int kbeg = ks * KCH, kend = kbeg + KCH;

    ull acc[4][4];
#pragma unroll
    for (int rb = 0; rb < 4; ++rb)
#pragma unroll
        for (int rj = 0; rj < 4; ++rj) acc[rb][rj] = 0ull;

    for (int k0 = kbeg; k0 < kend; k0 += 64) {
#pragma unroll
        for (int l = 0; l < 16; ++l) {
            int idx = tid + l * 256;
            int r = idx >> 6, cc = idx & 63;
            int k = k0 + cc;
            fs[r * 66 + cc] = (k < kend) ? g_feat[r * NFEAT + k] : 0.f;
            ws[r * 66 + cc] = (k < kend) ? wc1[(jt * 64 + r) * NFEAT + k] : 0.f;
        }
        __syncthreads();

        const ull* fs2 = reinterpret_cast<const ull*>(fs);
        const ull* ws2 = reinterpret_cast<const ull*>(ws);
#pragma unroll 4
        for (int cc2 = 0; cc2 < 32; ++cc2) {
            ull fv[4], wv[4];
#pragma unroll
            for (int r = 0; r < 4; ++r) fv[r] = fs2[(bq + 16 * r) * 33 + cc2];
#pragma unroll
            for (int r = 0; r < 4; ++r) wv[r] = ws2[(jq + 16 * r) * 33 + cc2];
#pragma unroll
            for (int rb = 0; rb < 4; ++rb)
#pragma unroll
                for (int rj = 0; rj < 4; ++rj)
                    acc[rb][rj] = fma2(fv[rb], wv[rj], acc[rb][rj]);
        }
        __syncthreads();
    }

#pragma unroll
    for (int rb = 0; rb < 4; ++rb) {
        int b = bq + 16 * rb;
#pragma unroll
        for (int rj = 0; rj < 4; ++rj) {
            int j = jt * 64 + jq + 16 * rj;
            float2 v = unpack2(acc[rb][rj]);
            g_part[(ks * NB + b) * 128 + j] = v.x + v.y;
        }
    }
}

// =====================================================================
// Kernel C: reduce partials (8-way split), bias1, ReLU, FC2
// =====================================================================
__global__ __launch_bounds__(1024) void fc2_kernel(
    const float* __restrict__ bc1, const float* __restrict__ wc2,
    const float* __restrict__ bc2, float* __restrict__ out)
{
    __shared__ float part[8][128];
    __shared__ float red[4];
    const int b = blockIdx.x;
    const int j = threadIdx.x & 127, r = threadIdx.x >> 7;   // r 0..7

    float s = 0.f;
#pragma unroll 5
    for (int ks = r; ks < KSPLIT; ks += 8)
        s += g_part[(ks * NB + b) * 128 + j];
    part[r][j] = s;
    __syncthreads();

    if (threadIdx.x < 128) {
        float t = bc1[j];
#pragma unroll
        for (int r2 = 0; r2 < 8; ++r2) t += part[r2][j];
        float v = fmaxf(t, 0.f) * wc2[j];
#pragma unroll
        for (int o = 16; o > 0; o >>= 1)
            v += __shfl_down_sync(0xffffffffu, v, o);
        if ((j & 31) == 0) red[j >> 5] = v;
    }
    __syncthreads();
    if (threadIdx.x == 0) out[b] = red[0] + red[1] + red[2] + red[3] + bc2[0];
}

// =====================================================================
extern "C" void kernel_launch(void* const* d_in, const int* in_sizes, int n_in,
                              void* d_out, int out_size)
{
    const float* x     = (const float*)d_in[0];
    const float* w1    = (const float*)d_in[1];
    const float* b1    = (const float*)d_in[2];
    const float* g1    = (const float*)d_in[3];
    const float* beta1 = (const float*)d_in[4];
    const float* m1    = (const float*)d_in[5];
    const float* v1    = (const float*)d_in[6];
    const float* w2    = (const float*)d_in[7];
    const float* b2    = (const float*)d_in[8];
    const float* g2    = (const float*)d_in[9];
    const float* beta2 = (const float*)d_in[10];
    const float* m2    = (const float*)d_in[11];
    const float* v2    = (const float*)d_in[12];
    const float* wc1   = (const float*)d_in[13];
    const float* bc1   = (const float*)d_in[14];
    const float* wc2   = (const float*)d_in[15];
    const float* bc2   = (const float*)d_in[16];
    float* out = (float*)d_out;

    prep_kernel<<<NC, 256>>>(w1, b1, g1, beta1, m1, v1,
                             w2, b2, g2, beta2, m2, v2);
    tower_kernel<<<NC * (NB / BPB), 320>>>(x);
    fc1_kernel<<<dim3(2, KSPLIT), 256>>>(wc1);
    fc2_kernel<<<NB, 1024>>>(bc1, wc2, bc2, out);
}